// round 2
// baseline (speedup 1.0000x reference)
#include <cuda_runtime.h>
#include <math.h>

#define B  32
#define L  2048
#define H  1024
#define K2 2048   // 2*H

#define GS 16     // g-splits for u partials
#define HS 16     // h-splits for v partials

// Scratch (no allocations allowed in kernel_launch)
__device__ float g_part_u[GS * B * H];   // 2 MB
__device__ float g_u[B * H];
__device__ float g_part_v[HS * B * K2];  // 4 MB
__device__ float g_v[B * K2];
__device__ float g_scores[B * L];

// ---------------------------------------------------------------------------
// Kernel A: partial u[b,h] = sum_{g in split} hid[b,g] * attn_W[g,h]
// grid (H/128, GS), block 128. aW read exactly once from DRAM (4 MB).
// ---------------------------------------------------------------------------
__global__ void k_u_partial(const float* __restrict__ hid,
                            const float* __restrict__ aW) {
    const int h  = blockIdx.x * 128 + threadIdx.x;
    const int g0 = blockIdx.y * (H / GS);           // 64 g per split
    __shared__ float s_hid[B][H / GS];              // 32 x 64 = 8 KB
    for (int i = threadIdx.x; i < B * (H / GS); i += 128) {
        int b = i / (H / GS), gg = i % (H / GS);
        s_hid[b][gg] = hid[b * H + g0 + gg];
    }
    __syncthreads();

    float acc[B];
#pragma unroll
    for (int b = 0; b < B; b++) acc[b] = 0.f;

    for (int gg = 0; gg < H / GS; gg++) {
        float a = aW[(size_t)(g0 + gg) * H + h];
#pragma unroll
        for (int b = 0; b < B; b++) acc[b] += a * s_hid[b][gg];
    }
    float* out = g_part_u + (size_t)blockIdx.y * (B * H);
#pragma unroll
    for (int b = 0; b < B; b++) out[b * H + h] = acc[b];
}

// Kernel B: u = sum over GS partials (deterministic reduce, float4)
__global__ void k_u_reduce() {
    int i = blockIdx.x * 256 + threadIdx.x;         // over B*H/4 = 8192
    const float4* p = (const float4*)g_part_u;
    float4 s = make_float4(0.f, 0.f, 0.f, 0.f);
#pragma unroll
    for (int q = 0; q < GS; q++) {
        float4 t = p[q * (B * H / 4) + i];
        s.x += t.x; s.y += t.y; s.z += t.z; s.w += t.w;
    }
    ((float4*)g_u)[i] = s;
}

// ---------------------------------------------------------------------------
// Kernel C: partial v[b,k] = sum_{h in split} u[b,h] * reduce_W[h,k]
// grid (K2/128, HS), block 128. rW read exactly once from DRAM (8 MB).
// ---------------------------------------------------------------------------
__global__ void k_v_partial(const float* __restrict__ rW) {
    const int k  = blockIdx.x * 128 + threadIdx.x;
    const int h0 = blockIdx.y * (H / HS);           // 64 h per split
    __shared__ float s_u[B][H / HS];                // 8 KB
    for (int i = threadIdx.x; i < B * (H / HS); i += 128) {
        int b = i / (H / HS), hh = i % (H / HS);
        s_u[b][hh] = g_u[b * H + h0 + hh];
    }
    __syncthreads();

    float acc[B];
#pragma unroll
    for (int b = 0; b < B; b++) acc[b] = 0.f;

    for (int hh = 0; hh < H / HS; hh++) {
        float r = rW[(size_t)(h0 + hh) * K2 + k];
#pragma unroll
        for (int b = 0; b < B; b++) acc[b] += r * s_u[b][hh];
    }
    float* out = g_part_v + (size_t)blockIdx.y * (B * K2);
#pragma unroll
    for (int b = 0; b < B; b++) out[b * K2 + k] = acc[b];
}

// Kernel D: v = sum over HS partials (float4)
__global__ void k_v_reduce() {
    int i = blockIdx.x * 256 + threadIdx.x;         // over B*K2/4 = 16384
    const float4* p = (const float4*)g_part_v;
    float4 s = make_float4(0.f, 0.f, 0.f, 0.f);
#pragma unroll
    for (int q = 0; q < HS; q++) {
        float4 t = p[q * (B * K2 / 4) + i];
        s.x += t.x; s.y += t.y; s.z += t.z; s.w += t.w;
    }
    ((float4*)g_v)[i] = s;
}

// ---------------------------------------------------------------------------
// Kernel E (the HBM-bound one): scores[b,l] = v[b] . enc[l,b,:]
// grid (L/32, B), block 256 = 8 warps, 4 rows/warp (sequential).
// Inner loop: two batches of 8 LDG.128 (32 regs live) -> no spills, MLP=8
// per warp in flight; 32 warps/SM via launch_bounds(256,4) give aggregate
// outstanding bytes >> the ~10 KB/SM needed to saturate HBM.
// v[b] staged once per block in smem (8 KB = 3% overhead, L2-resident).
// ---------------------------------------------------------------------------
__global__ void __launch_bounds__(256, 4) k_scores(const float* __restrict__ enc) {
    const int b    = blockIdx.y;
    const int w    = threadIdx.x >> 5;
    const int lane = threadIdx.x & 31;

    __shared__ float4 sv[K2 / 4];                   // 512 float4 = 8 KB
    const float4* v4 = (const float4*)(g_v + b * K2);
    for (int i = threadIdx.x; i < K2 / 4; i += 256) sv[i] = v4[i];
    __syncthreads();

    const int l0 = blockIdx.x * 32 + w * 4;
#pragma unroll 1
    for (int r = 0; r < 4; r++) {
        const int l = l0 + r;
        const float4* e4 = (const float4*)(enc + ((size_t)l * B + b) * K2);
        float ax = 0.f, ay = 0.f, az = 0.f, aw = 0.f;
#pragma unroll
        for (int jb = 0; jb < 16; jb += 8) {
            float4 e[8];
#pragma unroll
            for (int k = 0; k < 8; k++) e[k] = e4[lane + 32 * (jb + k)];
#pragma unroll
            for (int k = 0; k < 8; k++) {
                float4 vv = sv[lane + 32 * (jb + k)];
                ax += e[k].x * vv.x; ay += e[k].y * vv.y;
                az += e[k].z * vv.z; aw += e[k].w * vv.w;
            }
        }
        float acc = (ax + ay) + (az + aw);
#pragma unroll
        for (int o = 16; o; o >>= 1)
            acc += __shfl_xor_sync(0xffffffffu, acc, o);
        if (lane == 0) g_scores[b * L + l] = acc;
    }
}

// ---------------------------------------------------------------------------
// Kernel F: row softmax over L=2048 per batch. grid B, block 256, 8 elems/thr.
// ---------------------------------------------------------------------------
__global__ void k_softmax(float* __restrict__ out) {
    const int b    = blockIdx.x;
    const int tid  = threadIdx.x;
    const int w    = tid >> 5, lane = tid & 31;
    __shared__ float s_red[8];

    float vals[8];
    float m = -INFINITY;
#pragma unroll
    for (int i = 0; i < 8; i++) {
        vals[i] = g_scores[b * L + tid + i * 256];
        m = fmaxf(m, vals[i]);
    }
#pragma unroll
    for (int o = 16; o; o >>= 1) m = fmaxf(m, __shfl_xor_sync(0xffffffffu, m, o));
    if (lane == 0) s_red[w] = m;
    __syncthreads();
    float bm = s_red[0];
#pragma unroll
    for (int i = 1; i < 8; i++) bm = fmaxf(bm, s_red[i]);
    __syncthreads();

    float s = 0.f;
#pragma unroll
    for (int i = 0; i < 8; i++) { vals[i] = expf(vals[i] - bm); s += vals[i]; }
#pragma unroll
    for (int o = 16; o; o >>= 1) s += __shfl_xor_sync(0xffffffffu, s, o);
    if (lane == 0) s_red[w] = s;
    __syncthreads();
    float bs = 0.f;
#pragma unroll
    for (int i = 0; i < 8; i++) bs += s_red[i];

    const float inv = 1.f / bs;
#pragma unroll
    for (int i = 0; i < 8; i++) out[b * L + tid + i * 256] = vals[i] * inv;
}

// ---------------------------------------------------------------------------
extern "C" void kernel_launch(void* const* d_in, const int* in_sizes, int n_in,
                              void* d_out, int out_size) {
    const float* hid = (const float*)d_in[0];  // [B, H]
    const float* enc = (const float*)d_in[1];  // [L, B, 2H]
    const float* rW  = (const float*)d_in[2];  // [H, 2H]
    // d_in[3] = reduce_b, d_in[5] = attn_b: constant over l per batch ->
    // invariant under softmax, provably unused.
    const float* aW  = (const float*)d_in[4];  // [H, H]
    float* out = (float*)d_out;                // [B, L]

    k_u_partial<<<dim3(H / 128, GS), 128>>>(hid, aW);
    k_u_reduce<<<(B * H / 4) / 256, 256>>>();
    k_v_partial<<<dim3(K2 / 128, HS), 128>>>(rW);
    k_v_reduce<<<(B * K2 / 4) / 256, 256>>>();
    k_scores<<<dim3(L / 32, B), 256>>>(enc);
    k_softmax<<<B, 256>>>(out);
}

// round 3
// speedup vs baseline: 1.8991x; 1.8991x over previous
#include <cuda_runtime.h>
#include <math.h>

#define B  32
#define L  2048
#define H  1024
#define K2 2048   // 2*H

#define GS 16     // g-splits for u partials
#define HS 16     // h-splits for v partials

// Scratch (no allocations allowed in kernel_launch)
__device__ float g_part_u[GS * B * H];   // 2 MB (stays L2-hot)
__device__ float g_part_v[HS * B * K2];  // 4 MB
__device__ float g_v[B * K2];
__device__ float g_scores[B * L];

// ---------------------------------------------------------------------------
// Kernel 1: partial u[b,h] = sum_{g in split} hid[b,g] * attn_W[g,h]
// grid (H/128, GS), block 128. aW read exactly once from DRAM (4 MB).
// hid staged as float4 -> 8 LDS.128 per 4 g-steps instead of 32 scalar LDS.
// ---------------------------------------------------------------------------
__global__ void k_u_partial(const float* __restrict__ hid,
                            const float* __restrict__ aW) {
    const int h  = blockIdx.x * 128 + threadIdx.x;
    const int g0 = blockIdx.y * (H / GS);           // 64 g per split
    __shared__ float4 s_hid[B][16];                 // 32 x 64 floats = 8 KB
    for (int i = threadIdx.x; i < B * 16; i += 128) {
        int b = i >> 4, c = i & 15;
        s_hid[b][c] = ((const float4*)(hid + b * H + g0))[c];
    }
    __syncthreads();

    float acc[B];
#pragma unroll
    for (int b = 0; b < B; b++) acc[b] = 0.f;

#pragma unroll 4
    for (int c = 0; c < 16; c++) {
        const float* ap = aW + (size_t)(g0 + 4 * c) * H + h;
        float a0 = ap[0], a1 = ap[H], a2 = ap[2 * H], a3 = ap[3 * H];
#pragma unroll
        for (int b = 0; b < B; b++) {
            float4 h4 = s_hid[b][c];
            acc[b] += a0 * h4.x + a1 * h4.y + a2 * h4.z + a3 * h4.w;
        }
    }
    float* out = g_part_u + (size_t)blockIdx.y * (B * H);
#pragma unroll
    for (int b = 0; b < B; b++) out[b * H + h] = acc[b];
}

// ---------------------------------------------------------------------------
// Kernel 2: partial v[b,k] = sum_{h in split} u[b,h] * reduce_W[h,k]
// u-reduce FUSED into the staging loop: s_u = sum_p g_part_u[p] (L2-hot).
// grid (K2/128, HS), block 128. rW read exactly once from DRAM (8 MB).
// ---------------------------------------------------------------------------
__global__ void k_v_partial(const float* __restrict__ rW) {
    const int k  = blockIdx.x * 128 + threadIdx.x;
    const int h0 = blockIdx.y * (H / HS);           // 64 h per split
    __shared__ float4 s_u[B][16];                   // 8 KB
    for (int i = threadIdx.x; i < B * 16; i += 128) {
        int b = i >> 4, c = i & 15;
        float4 s = make_float4(0.f, 0.f, 0.f, 0.f);
        const float4* pu = (const float4*)g_part_u + (size_t)b * (H / 4) + (h0 / 4) + c;
#pragma unroll
        for (int p = 0; p < GS; p++) {
            float4 t = pu[(size_t)p * (B * H / 4)];
            s.x += t.x; s.y += t.y; s.z += t.z; s.w += t.w;
        }
        s_u[b][c] = s;
    }
    __syncthreads();

    float acc[B];
#pragma unroll
    for (int b = 0; b < B; b++) acc[b] = 0.f;

#pragma unroll 4
    for (int c = 0; c < 16; c++) {
        const float* rp = rW + (size_t)(h0 + 4 * c) * K2 + k;
        float r0 = rp[0], r1 = rp[K2], r2 = rp[2 * K2], r3 = rp[3 * K2];
#pragma unroll
        for (int b = 0; b < B; b++) {
            float4 u4 = s_u[b][c];
            acc[b] += r0 * u4.x + r1 * u4.y + r2 * u4.z + r3 * u4.w;
        }
    }
    float* out = g_part_v + (size_t)blockIdx.y * (B * K2);
#pragma unroll
    for (int b = 0; b < B; b++) out[b * K2 + k] = acc[b];
}

// Kernel 3: v = sum over HS partials (float4, deterministic)
__global__ void k_v_reduce() {
    int i = blockIdx.x * 256 + threadIdx.x;         // over B*K2/4 = 16384
    const float4* p = (const float4*)g_part_v;
    float4 s = make_float4(0.f, 0.f, 0.f, 0.f);
#pragma unroll
    for (int q = 0; q < HS; q++) {
        float4 t = p[(size_t)q * (B * K2 / 4) + i];
        s.x += t.x; s.y += t.y; s.z += t.z; s.w += t.w;
    }
    ((float4*)g_v)[i] = s;
}

// ---------------------------------------------------------------------------
// Kernel 4 (HBM-bound): scores[b,l] = v[b] . enc[l,b,:]
// One row per warp, grid (L/8, B), block 256 = 8 warps.
// All 16 LDG.128 per lane issued back-to-back (single batch, max MLP),
// streaming hint (__ldcs) since enc has zero reuse. v[b] staged in 8 KB smem
// (12.5% extra L2-side reads, zero extra DRAM).
// ---------------------------------------------------------------------------
__global__ void __launch_bounds__(256) k_scores(const float* __restrict__ enc) {
    const int b    = blockIdx.y;
    const int w    = threadIdx.x >> 5;
    const int lane = threadIdx.x & 31;

    __shared__ float4 sv[K2 / 4];                   // 512 float4 = 8 KB
    const float4* v4 = (const float4*)(g_v + b * K2);
    for (int i = threadIdx.x; i < K2 / 4; i += 256) sv[i] = v4[i];
    __syncthreads();

    const int l = blockIdx.x * 8 + w;
    const float4* e4 = (const float4*)(enc + ((size_t)l * B + b) * K2);

    float4 e[16];
#pragma unroll
    for (int j = 0; j < 16; j++) e[j] = __ldcs(&e4[lane + 32 * j]);

    float ax = 0.f, ay = 0.f, az = 0.f, aw = 0.f;
#pragma unroll
    for (int j = 0; j < 16; j++) {
        float4 vv = sv[lane + 32 * j];
        ax += e[j].x * vv.x; ay += e[j].y * vv.y;
        az += e[j].z * vv.z; aw += e[j].w * vv.w;
    }
    float acc = (ax + ay) + (az + aw);
#pragma unroll
    for (int o = 16; o; o >>= 1)
        acc += __shfl_xor_sync(0xffffffffu, acc, o);
    if (lane == 0) g_scores[b * L + l] = acc;
}

// ---------------------------------------------------------------------------
// Kernel 5: row softmax over L=2048 per batch. grid B, block 256.
// ---------------------------------------------------------------------------
__global__ void k_softmax(float* __restrict__ out) {
    const int b    = blockIdx.x;
    const int tid  = threadIdx.x;
    const int w    = tid >> 5, lane = tid & 31;
    __shared__ float s_red[8];

    float vals[8];
    float m = -INFINITY;
#pragma unroll
    for (int i = 0; i < 8; i++) {
        vals[i] = g_scores[b * L + tid + i * 256];
        m = fmaxf(m, vals[i]);
    }
#pragma unroll
    for (int o = 16; o; o >>= 1) m = fmaxf(m, __shfl_xor_sync(0xffffffffu, m, o));
    if (lane == 0) s_red[w] = m;
    __syncthreads();
    float bm = s_red[0];
#pragma unroll
    for (int i = 1; i < 8; i++) bm = fmaxf(bm, s_red[i]);
    __syncthreads();

    float s = 0.f;
#pragma unroll
    for (int i = 0; i < 8; i++) { vals[i] = expf(vals[i] - bm); s += vals[i]; }
#pragma unroll
    for (int o = 16; o; o >>= 1) s += __shfl_xor_sync(0xffffffffu, s, o);
    if (lane == 0) s_red[w] = s;
    __syncthreads();
    float bs = 0.f;
#pragma unroll
    for (int i = 0; i < 8; i++) bs += s_red[i];

    const float inv = 1.f / bs;
#pragma unroll
    for (int i = 0; i < 8; i++) out[b * L + tid + i * 256] = vals[i] * inv;
}

// ---------------------------------------------------------------------------
extern "C" void kernel_launch(void* const* d_in, const int* in_sizes, int n_in,
                              void* d_out, int out_size) {
    const float* hid = (const float*)d_in[0];  // [B, H]
    const float* enc = (const float*)d_in[1];  // [L, B, 2H]
    const float* rW  = (const float*)d_in[2];  // [H, 2H]
    // d_in[3] = reduce_b, d_in[5] = attn_b: constant over l per batch ->
    // invariant under softmax, provably unused.
    const float* aW  = (const float*)d_in[4];  // [H, H]
    float* out = (float*)d_out;                // [B, L]

    k_u_partial<<<dim3(H / 128, GS), 128>>>(hid, aW);
    k_v_partial<<<dim3(K2 / 128, HS), 128>>>(rW);
    k_v_reduce<<<(B * K2 / 4) / 256, 256>>>();
    k_scores<<<dim3(L / 8, B), 256>>>(enc);
    k_softmax<<<B, 256>>>(out);
}

// round 4
// speedup vs baseline: 1.9358x; 1.0193x over previous
#include <cuda_runtime.h>
#include <math.h>

#define B  32
#define L  2048
#define H  1024
#define K2 2048   // 2*H

#define GS 32     // g-splits for u partials
#define HS 32     // h-splits for v partials

// Scratch (no allocations allowed in kernel_launch)
__device__ float g_part_u[GS * B * H];   // 4 MB (stays L2-hot)
__device__ float g_part_v[HS * B * K2];  // 8 MB
__device__ float g_v[B * K2];
__device__ float g_scores[B * L];

// ---------------------------------------------------------------------------
// Kernel 1: partial u[b,h] = sum_{g in split} hid[b,g] * attn_W[g,h]
// grid (H/128, GS)=(8,32)=256 blocks, block 128. aW read once from DRAM (4MB).
// ---------------------------------------------------------------------------
__global__ void k_u_partial(const float* __restrict__ hid,
                            const float* __restrict__ aW) {
    const int h  = blockIdx.x * 128 + threadIdx.x;
    const int g0 = blockIdx.y * (H / GS);           // 32 g per split
    __shared__ float4 s_hid[B][8];                  // 32 x 32 floats = 4 KB
    for (int i = threadIdx.x; i < B * 8; i += 128) {
        int b = i >> 3, c = i & 7;
        s_hid[b][c] = ((const float4*)(hid + b * H + g0))[c];
    }
    __syncthreads();

    float acc[B];
#pragma unroll
    for (int b = 0; b < B; b++) acc[b] = 0.f;

#pragma unroll 4
    for (int c = 0; c < 8; c++) {
        const float* ap = aW + (size_t)(g0 + 4 * c) * H + h;
        float a0 = ap[0], a1 = ap[H], a2 = ap[2 * H], a3 = ap[3 * H];
#pragma unroll
        for (int b = 0; b < B; b++) {
            float4 h4 = s_hid[b][c];
            acc[b] += a0 * h4.x + a1 * h4.y + a2 * h4.z + a3 * h4.w;
        }
    }
    float* out = g_part_u + (size_t)blockIdx.y * (B * H);
#pragma unroll
    for (int b = 0; b < B; b++) out[b * H + h] = acc[b];
}

// ---------------------------------------------------------------------------
// Kernel 2: partial v[b,k] = sum_{h in split} u[b,h] * reduce_W[h,k]
// u-reduce FUSED into the staging loop (sums GS partials from L2-hot buffer).
// grid (K2/128, HS)=(16,32)=512 blocks, block 128. rW read once (8 MB).
// ---------------------------------------------------------------------------
__global__ void k_v_partial(const float* __restrict__ rW) {
    const int k  = blockIdx.x * 128 + threadIdx.x;
    const int h0 = blockIdx.y * (H / HS);           // 32 h per split
    __shared__ float4 s_u[B][8];                    // 4 KB
    for (int i = threadIdx.x; i < B * 8; i += 128) {
        int b = i >> 3, c = i & 7;
        float4 s = make_float4(0.f, 0.f, 0.f, 0.f);
        const float4* pu = (const float4*)g_part_u + (size_t)b * (H / 4) + (h0 / 4) + c;
#pragma unroll
        for (int p = 0; p < GS; p++) {
            float4 t = pu[(size_t)p * (B * H / 4)];
            s.x += t.x; s.y += t.y; s.z += t.z; s.w += t.w;
        }
        s_u[b][c] = s;
    }
    __syncthreads();

    float acc[B];
#pragma unroll
    for (int b = 0; b < B; b++) acc[b] = 0.f;

#pragma unroll 4
    for (int c = 0; c < 8; c++) {
        const float* rp = rW + (size_t)(h0 + 4 * c) * K2 + k;
        float r0 = rp[0], r1 = rp[K2], r2 = rp[2 * K2], r3 = rp[3 * K2];
#pragma unroll
        for (int b = 0; b < B; b++) {
            float4 u4 = s_u[b][c];
            acc[b] += r0 * u4.x + r1 * u4.y + r2 * u4.z + r3 * u4.w;
        }
    }
    float* out = g_part_v + (size_t)blockIdx.y * (B * K2);
#pragma unroll
    for (int b = 0; b < B; b++) out[b * K2 + k] = acc[b];
}

// Kernel 3: v = sum over HS partials (float4, deterministic, L2-hot).
// 128 blocks x 128 threads -> all SMs busy (was 64 blocks / occ 12%).
__global__ void k_v_reduce() {
    int i = blockIdx.x * 128 + threadIdx.x;         // over B*K2/4 = 16384
    const float4* p = (const float4*)g_part_v;
    float4 s = make_float4(0.f, 0.f, 0.f, 0.f);
#pragma unroll
    for (int q = 0; q < HS; q++) {
        float4 t = p[(size_t)q * (B * K2 / 4) + i];
        s.x += t.x; s.y += t.y; s.z += t.z; s.w += t.w;
    }
    ((float4*)g_v)[i] = s;
}

// ---------------------------------------------------------------------------
// Kernel 4 (HBM-bound): scores[b,l] = v[b] . enc[l,b,:]
// One row per warp, grid (L/8, B), block 256 = 8 warps.
// launch_bounds(256,8) caps regs at 32 -> 100% theoretical occupancy.
// ---------------------------------------------------------------------------
__global__ void __launch_bounds__(256, 8) k_scores(const float* __restrict__ enc) {
    const int b    = blockIdx.y;
    const int w    = threadIdx.x >> 5;
    const int lane = threadIdx.x & 31;

    __shared__ float4 sv[K2 / 4];                   // 512 float4 = 8 KB
    const float4* v4 = (const float4*)(g_v + b * K2);
    for (int i = threadIdx.x; i < K2 / 4; i += 256) sv[i] = v4[i];
    __syncthreads();

    const int l = blockIdx.x * 8 + w;
    const float4* e4 = (const float4*)(enc + ((size_t)l * B + b) * K2);

    float4 e[16];
#pragma unroll
    for (int j = 0; j < 16; j++) e[j] = __ldcs(&e4[lane + 32 * j]);

    float ax = 0.f, ay = 0.f, az = 0.f, aw = 0.f;
#pragma unroll
    for (int j = 0; j < 16; j++) {
        float4 vv = sv[lane + 32 * j];
        ax += e[j].x * vv.x; ay += e[j].y * vv.y;
        az += e[j].z * vv.z; aw += e[j].w * vv.w;
    }
    float acc = (ax + ay) + (az + aw);
#pragma unroll
    for (int o = 16; o; o >>= 1)
        acc += __shfl_xor_sync(0xffffffffu, acc, o);
    if (lane == 0) g_scores[b * L + l] = acc;
}

// ---------------------------------------------------------------------------
// Kernel 5: row softmax over L=2048 per batch. grid B, block 256.
// ---------------------------------------------------------------------------
__global__ void k_softmax(float* __restrict__ out) {
    const int b    = blockIdx.x;
    const int tid  = threadIdx.x;
    const int w    = tid >> 5, lane = tid & 31;
    __shared__ float s_red[8];

    float vals[8];
    float m = -INFINITY;
#pragma unroll
    for (int i = 0; i < 8; i++) {
        vals[i] = g_scores[b * L + tid + i * 256];
        m = fmaxf(m, vals[i]);
    }
#pragma unroll
    for (int o = 16; o; o >>= 1) m = fmaxf(m, __shfl_xor_sync(0xffffffffu, m, o));
    if (lane == 0) s_red[w] = m;
    __syncthreads();
    float bm = s_red[0];
#pragma unroll
    for (int i = 1; i < 8; i++) bm = fmaxf(bm, s_red[i]);
    __syncthreads();

    float s = 0.f;
#pragma unroll
    for (int i = 0; i < 8; i++) { vals[i] = expf(vals[i] - bm); s += vals[i]; }
#pragma unroll
    for (int o = 16; o; o >>= 1) s += __shfl_xor_sync(0xffffffffu, s, o);
    if (lane == 0) s_red[w] = s;
    __syncthreads();
    float bs = 0.f;
#pragma unroll
    for (int i = 0; i < 8; i++) bs += s_red[i];

    const float inv = 1.f / bs;
#pragma unroll
    for (int i = 0; i < 8; i++) out[b * L + tid + i * 256] = vals[i] * inv;
}

// ---------------------------------------------------------------------------
extern "C" void kernel_launch(void* const* d_in, const int* in_sizes, int n_in,
                              void* d_out, int out_size) {
    const float* hid = (const float*)d_in[0];  // [B, H]
    const float* enc = (const float*)d_in[1];  // [L, B, 2H]
    const float* rW  = (const float*)d_in[2];  // [H, 2H]
    // d_in[3] = reduce_b, d_in[5] = attn_b: constant over l per batch ->
    // invariant under softmax, provably unused.
    const float* aW  = (const float*)d_in[4];  // [H, H]
    float* out = (float*)d_out;                // [B, L]

    k_u_partial<<<dim3(H / 128, GS), 128>>>(hid, aW);
    k_v_partial<<<dim3(K2 / 128, HS), 128>>>(rW);
    k_v_reduce<<<(B * K2 / 4) / 128, 128>>>();
    k_scores<<<dim3(L / 8, B), 256>>>(enc);
    k_softmax<<<B, 256>>>(out);
}